// round 2
// baseline (speedup 1.0000x reference)
#include <cuda_runtime.h>
#include <math.h>

#define Nn 100000
#define Ee 1600000
#define Dd 128
#define Hh 8
#define Ff 512

// ---------------- scratch (static device globals; no allocation) ----------------
__device__ float g_q[(size_t)Nn * Dd];
__device__ float g_k[(size_t)Nn * Dd];
__device__ float g_v[(size_t)Nn * Dd];
__device__ float g_ex[(size_t)Ee * Hh];
__device__ float g_denom[(size_t)Nn * Hh];
__device__ float g_rst[(size_t)Nn * Dd];    // feat + aggregated messages (pre-LN)
__device__ float g_rstn[(size_t)Nn * Dd];   // post-LN1
__device__ float g_hid[(size_t)Nn * Ff];    // FFN hidden
__device__ float g_f2[(size_t)Nn * Dd];     // rstn + ffn (pre-LN2)

// ---------------- init: rst = feat, denom = 0 (must run every graph replay) ----
__global__ void init_kernel(const float* __restrict__ feat) {
    int i = blockIdx.x * blockDim.x + threadIdx.x;
    if (i < Nn * Dd) g_rst[i] = feat[i];
    if (i < Nn * Hh) g_denom[i] = 0.f;
}

// ---------------- generic tiled SGEMM: C = A[M,K] @ W[K,Nc] + bias -------------
// MODE 0: plain   MODE 1: PReLU(alpha per-col)   MODE 2: += res[row, col]
template <int MODE>
__global__ void gemm64(const float* __restrict__ A, const float* __restrict__ W,
                       const float* __restrict__ bias, const float* __restrict__ alpha,
                       const float* __restrict__ res, float* __restrict__ C,
                       int M, int Nc, int K) {
    constexpr int BM = 64, BN = 64, BK = 16;
    __shared__ float As[BK][BM];
    __shared__ float Ws[BK][BN];
    const int t  = threadIdx.x;       // 256
    const int tx = t & 15, ty = t >> 4;
    const int bm = blockIdx.y * BM, bn = blockIdx.x * BN;

    float acc[4][4] = {};

    const int arow = t >> 2;            // 0..63
    const int acol = (t & 3) * 4;       // 0,4,8,12
    const int wrow = t >> 4;            // 0..15
    const int wcol = (t & 15) * 4;      // 0..60

    for (int kk = 0; kk < K; kk += BK) {
        float4 a4 = make_float4(0.f, 0.f, 0.f, 0.f);
        const int grow = bm + arow;
        if (grow < M) a4 = *(const float4*)&A[(size_t)grow * K + kk + acol];
        As[acol + 0][arow] = a4.x;
        As[acol + 1][arow] = a4.y;
        As[acol + 2][arow] = a4.z;
        As[acol + 3][arow] = a4.w;
        *(float4*)&Ws[wrow][wcol] =
            *(const float4*)&W[(size_t)(kk + wrow) * Nc + bn + wcol];
        __syncthreads();

#pragma unroll
        for (int k = 0; k < BK; k++) {
            const float4 av = *(const float4*)&As[k][ty * 4];
            const float4 wv = *(const float4*)&Ws[k][tx * 4];
            const float a[4] = {av.x, av.y, av.z, av.w};
            const float w[4] = {wv.x, wv.y, wv.z, wv.w};
#pragma unroll
            for (int i = 0; i < 4; i++)
#pragma unroll
                for (int j = 0; j < 4; j++) acc[i][j] += a[i] * w[j];
        }
        __syncthreads();
    }

#pragma unroll
    for (int i = 0; i < 4; i++) {
        const int row = bm + ty * 4 + i;
        if (row >= M) continue;
#pragma unroll
        for (int j = 0; j < 4; j++) {
            const int col = bn + tx * 4 + j;
            float c = acc[i][j] + bias[col];
            if (MODE == 1) c = c > 0.f ? c : alpha[col] * c;
            if (MODE == 2) c += res[(size_t)row * Nc + col];
            C[(size_t)row * Nc + col] = c;
        }
    }
}

// ---------------- edge scores: warp per edge ----------------
// e[h] = <k[src], q[dst]>_head / sqrt(D); ex = exp(e); denom[dst,h] += ex
// (segment-max subtraction cancels exactly in ex/denom; scores ~N(0,0.35), no overflow)
__global__ void edge_score(const int* __restrict__ src, const int* __restrict__ dst) {
    const int idx = blockIdx.x * blockDim.x + threadIdx.x;
    const int e = idx >> 5;
    if (e >= Ee) return;
    const int lane = idx & 31;
    const int s = src[e], d = dst[e];
    const float4 kv = *(const float4*)&g_k[(size_t)s * Dd + lane * 4];
    const float4 qv = *(const float4*)&g_q[(size_t)d * Dd + lane * 4];
    float p = kv.x * qv.x + kv.y * qv.y + kv.z * qv.z + kv.w * qv.w;
    p += __shfl_xor_sync(0xffffffffu, p, 1);
    p += __shfl_xor_sync(0xffffffffu, p, 2);   // reduced over the 4 lanes of one head
    if ((lane & 3) == 0) {
        const int h = lane >> 2;
        const float ee = __expf(p * 0.08838834764831845f);  // 1/sqrt(128)
        g_ex[(size_t)e * Hh + h] = ee;
        atomicAdd(&g_denom[(size_t)d * Hh + h], ee);
    }
}

// ---------------- aggregation: warp per edge, scatter a*v[src] into rst[dst] ---
__global__ void edge_aggr(const int* __restrict__ src, const int* __restrict__ dst) {
    const int idx = blockIdx.x * blockDim.x + threadIdx.x;
    const int e = idx >> 5;
    if (e >= Ee) return;
    const int lane = idx & 31;
    const int s = src[e], d = dst[e];
    const int h = lane >> 2;
    const float a = g_ex[(size_t)e * Hh + h] / g_denom[(size_t)d * Hh + h];
    const float4 vv = *(const float4*)&g_v[(size_t)s * Dd + lane * 4];
    float* out = &g_rst[(size_t)d * Dd + lane * 4];
    atomicAdd(out + 0, vv.x * a);
    atomicAdd(out + 1, vv.y * a);
    atomicAdd(out + 2, vv.z * a);
    atomicAdd(out + 3, vv.w * a);
}

// ---------------- layernorm over last dim (128), block per node ----------------
__global__ void ln_kernel(const float* __restrict__ x, const float* __restrict__ g,
                          const float* __restrict__ b, float* __restrict__ y) {
    const int n = blockIdx.x;
    const int t = threadIdx.x;  // 128
    const float v = x[(size_t)n * Dd + t];
    float s = v, s2 = v * v;
#pragma unroll
    for (int o = 16; o > 0; o >>= 1) {
        s  += __shfl_xor_sync(0xffffffffu, s, o);
        s2 += __shfl_xor_sync(0xffffffffu, s2, o);
    }
    __shared__ float red[8];
    const int w = t >> 5, lane = t & 31;
    if (lane == 0) { red[w] = s; red[4 + w] = s2; }
    __syncthreads();
    if (t == 0) {
        const float S  = red[0] + red[1] + red[2] + red[3];
        const float S2 = red[4] + red[5] + red[6] + red[7];
        const float mu = S * (1.f / Dd);
        const float var = S2 * (1.f / Dd) - mu * mu;
        red[0] = mu;
        red[1] = rsqrtf(var + 1e-5f);
    }
    __syncthreads();
    const float mu = red[0], r = red[1];
    y[(size_t)n * Dd + t] = (v - mu) * r * g[t] + b[t];
}

// ---------------- launch ----------------
extern "C" void kernel_launch(void* const* d_in, const int* in_sizes, int n_in,
                              void* d_out, int out_size) {
    const float* feat  = (const float*)d_in[0];
    const int*   src   = (const int*)d_in[1];
    const int*   dst   = (const int*)d_in[2];
    const float* Wq    = (const float*)d_in[3];
    const float* bq    = (const float*)d_in[4];
    const float* Wk    = (const float*)d_in[5];
    const float* bk    = (const float*)d_in[6];
    const float* Wv    = (const float*)d_in[7];
    const float* bv    = (const float*)d_in[8];
    const float* ln_g  = (const float*)d_in[9];
    const float* ln_b  = (const float*)d_in[10];
    const float* W1    = (const float*)d_in[11];
    const float* b1    = (const float*)d_in[12];
    const float* alpha = (const float*)d_in[13];
    const float* W2    = (const float*)d_in[14];
    const float* b2    = (const float*)d_in[15];
    float* out = (float*)d_out;

    float *pq, *pk, *pv, *prst, *prstn, *phid, *pf2;
    cudaGetSymbolAddress((void**)&pq, g_q);
    cudaGetSymbolAddress((void**)&pk, g_k);
    cudaGetSymbolAddress((void**)&pv, g_v);
    cudaGetSymbolAddress((void**)&prst, g_rst);
    cudaGetSymbolAddress((void**)&prstn, g_rstn);
    cudaGetSymbolAddress((void**)&phid, g_hid);
    cudaGetSymbolAddress((void**)&pf2, g_f2);

    const int MB = (Nn + 63) / 64;  // 1563

    init_kernel<<<(Nn * Dd + 255) / 256, 256>>>(feat);

    gemm64<0><<<dim3(Dd / 64, MB), 256>>>(feat, Wq, bq, nullptr, nullptr, pq, Nn, Dd, Dd);
    gemm64<0><<<dim3(Dd / 64, MB), 256>>>(feat, Wk, bk, nullptr, nullptr, pk, Nn, Dd, Dd);
    gemm64<0><<<dim3(Dd / 64, MB), 256>>>(feat, Wv, bv, nullptr, nullptr, pv, Nn, Dd, Dd);

    const int ethreads = Ee * 32;
    edge_score<<<(ethreads + 255) / 256, 256>>>(src, dst);
    edge_aggr<<<(ethreads + 255) / 256, 256>>>(src, dst);

    ln_kernel<<<Nn, 128>>>(prst, ln_g, ln_b, prstn);

    gemm64<1><<<dim3(Ff / 64, MB), 256>>>(prstn, W1, b1, alpha, nullptr, phid, Nn, Ff, Dd);
    gemm64<2><<<dim3(Dd / 64, MB), 256>>>(phid, W2, b2, nullptr, prstn, pf2, Nn, Dd, Ff);

    ln_kernel<<<Nn, 128>>>(pf2, ln_g, ln_b, out);
}

// round 4
// speedup vs baseline: 1.6246x; 1.6246x over previous
#include <cuda_runtime.h>
#include <mma.h>
#include <math.h>

using namespace nvcuda;

#define Nn 100000
#define Ee 1600000
#define Dd 128
#define Hh 8
#define Ff 512

// ---------------- scratch (static device globals; no allocation) ----------------
__device__ float g_q[(size_t)Nn * Dd];
__device__ float g_k[(size_t)Nn * Dd];
__device__ float g_v[(size_t)Nn * Dd];
__device__ float g_acc[(size_t)Nn * Dd];    // sum over edges of ex * v[src]
__device__ float g_denom[(size_t)Nn * Hh];  // sum over edges of ex
__device__ float g_rstn[(size_t)Nn * Dd];   // post-LN1
__device__ float g_hid[(size_t)Nn * Ff];    // FFN hidden
__device__ float g_f2[(size_t)Nn * Dd];     // rstn + ffn (pre-LN2)

// ---------------- init: acc = 0, denom = 0 (must run every graph replay) -------
__global__ void init_kernel() {
    int i = blockIdx.x * blockDim.x + threadIdx.x;
    if (i < Nn * Dd) g_acc[i] = 0.f;
    if (i < Nn * Hh) g_denom[i] = 0.f;
}

// ---------------- TF32 tensor-core GEMM: C = A[M,K] @ W[K,Nc] + bias ------------
// MODE 0: plain   MODE 1: PReLU(alpha per-col)   MODE 2: += res[row, col]
// Block tile 128(M) x 64(N), BK=32, 8 warps (warp tile 32x32).
struct SmemAB {
    float As[128][36];  // padded: 36 % 32 = 4 banks offset
    float Bs[32][68];
};
union SmemU {
    SmemAB ab;
    float Cs[128][68];
};

template <int MODE>
__global__ void __launch_bounds__(256) gemm_tc(
    const float* __restrict__ A, const float* __restrict__ W,
    const float* __restrict__ bias, const float* __restrict__ alpha,
    const float* __restrict__ res, float* __restrict__ C,
    int M, int Nc, int K) {
    __shared__ SmemU u;

    const int t = threadIdx.x;
    const int w = t >> 5;
    const int warp_m = w & 3;   // 0..3  -> 32 rows each
    const int warp_n = w >> 2;  // 0..1  -> 32 cols each
    const int bm = blockIdx.y * 128, bn = blockIdx.x * 64;

    wmma::fragment<wmma::accumulator, 16, 16, 8, float> cf[2][2];
#pragma unroll
    for (int i = 0; i < 2; i++)
#pragma unroll
        for (int j = 0; j < 2; j++) wmma::fill_fragment(cf[i][j], 0.f);

    for (int kk = 0; kk < K; kk += 32) {
        __syncthreads();
        // load A tile: 128 x 32  (1024 float4, 4 per thread)
#pragma unroll
        for (int i = 0; i < 4; i++) {
            const int idx = t + i * 256;
            const int row = idx >> 3;
            const int col = (idx & 7) * 4;
            float4 a4 = make_float4(0.f, 0.f, 0.f, 0.f);
            const int grow = bm + row;
            if (grow < M) a4 = *(const float4*)&A[(size_t)grow * K + kk + col];
            u.ab.As[row][col + 0] = a4.x;
            u.ab.As[row][col + 1] = a4.y;
            u.ab.As[row][col + 2] = a4.z;
            u.ab.As[row][col + 3] = a4.w;
        }
        // load B tile: 32 x 64  (512 float4, 2 per thread)
#pragma unroll
        for (int i = 0; i < 2; i++) {
            const int idx = t + i * 256;
            const int row = idx >> 4;
            const int col = (idx & 15) * 4;
            const float4 b4 = *(const float4*)&W[(size_t)(kk + row) * Nc + bn + col];
            u.ab.Bs[row][col + 0] = b4.x;
            u.ab.Bs[row][col + 1] = b4.y;
            u.ab.Bs[row][col + 2] = b4.z;
            u.ab.Bs[row][col + 3] = b4.w;
        }
        __syncthreads();

#pragma unroll
        for (int ks = 0; ks < 4; ks++) {
            const int k = ks * 8;
            wmma::fragment<wmma::matrix_a, 16, 16, 8, wmma::precision::tf32, wmma::row_major> af[2];
            wmma::fragment<wmma::matrix_b, 16, 16, 8, wmma::precision::tf32, wmma::row_major> bf[2];
#pragma unroll
            for (int i = 0; i < 2; i++) {
                wmma::load_matrix_sync(af[i], &u.ab.As[warp_m * 32 + i * 16][k], 36);
#pragma unroll
                for (int x = 0; x < af[i].num_elements; x++)
                    af[i].x[x] = wmma::__float_to_tf32(af[i].x[x]);
            }
#pragma unroll
            for (int j = 0; j < 2; j++) {
                wmma::load_matrix_sync(bf[j], &u.ab.Bs[k][warp_n * 32 + j * 16], 68);
#pragma unroll
                for (int x = 0; x < bf[j].num_elements; x++)
                    bf[j].x[x] = wmma::__float_to_tf32(bf[j].x[x]);
            }
#pragma unroll
            for (int i = 0; i < 2; i++)
#pragma unroll
                for (int j = 0; j < 2; j++)
                    wmma::mma_sync(cf[i][j], af[i], bf[j], cf[i][j]);
        }
    }

    __syncthreads();
#pragma unroll
    for (int i = 0; i < 2; i++)
#pragma unroll
        for (int j = 0; j < 2; j++)
            wmma::store_matrix_sync(&u.Cs[warp_m * 32 + i * 16][warp_n * 32 + j * 16],
                                    cf[i][j], 68, wmma::mem_row_major);
    __syncthreads();

    // epilogue: 128x64 elems = 2048 float4, 8 per thread
#pragma unroll
    for (int i = 0; i < 8; i++) {
        const int idx = t + i * 256;
        const int row = idx >> 4;
        const int col = (idx & 15) * 4;
        const int grow = bm + row;
        if (grow >= M) continue;
        float c[4];
#pragma unroll
        for (int x = 0; x < 4; x++) {
            c[x] = u.Cs[row][col + x] + bias[bn + col + x];
            if (MODE == 1) {
                const float al = alpha[bn + col + x];
                c[x] = c[x] > 0.f ? c[x] : al * c[x];
            }
            if (MODE == 2) c[x] += res[(size_t)grow * Nc + bn + col + x];
        }
        *(float4*)&C[(size_t)grow * Nc + bn + col] =
            make_float4(c[0], c[1], c[2], c[3]);
    }
}

// ---------------- fused edge pass: warp per edge -------------------------------
// e[h] = <k[src], q[dst]>_head / sqrt(D); ex = exp(e)
// denom[dst,h] += ex ; acc[dst] += ex * v[src]   (softmax division deferred)
__global__ void edge_fused(const int* __restrict__ src, const int* __restrict__ dst) {
    const long long idx = (long long)blockIdx.x * blockDim.x + threadIdx.x;
    const int e = (int)(idx >> 5);
    if (e >= Ee) return;
    const int lane = (int)(idx & 31);
    const int s = src[e], d = dst[e];
    const float4 kv = *(const float4*)&g_k[(size_t)s * Dd + lane * 4];
    const float4 qv = *(const float4*)&g_q[(size_t)d * Dd + lane * 4];
    const float4 vv = *(const float4*)&g_v[(size_t)s * Dd + lane * 4];
    float p = kv.x * qv.x + kv.y * qv.y + kv.z * qv.z + kv.w * qv.w;
    p += __shfl_xor_sync(0xffffffffu, p, 1);
    p += __shfl_xor_sync(0xffffffffu, p, 2);  // all 4 lanes of a head hold the dot
    const float ee = __expf(p * 0.08838834764831845f);  // 1/sqrt(128)
    if ((lane & 3) == 0)
        atomicAdd(&g_denom[(size_t)d * Hh + (lane >> 2)], ee);
    float* out = &g_acc[(size_t)d * Dd + lane * 4];
    asm volatile("red.global.add.v4.f32 [%0], {%1,%2,%3,%4};" ::
                     "l"(out), "f"(vv.x * ee), "f"(vv.y * ee), "f"(vv.z * ee), "f"(vv.w * ee)
                 : "memory");
}

// ---------------- LN1: rst = LN(feat + acc/denom) ------------------------------
__global__ void ln1_kernel(const float* __restrict__ feat, const float* __restrict__ g,
                           const float* __restrict__ b, float* __restrict__ y) {
    const int n = blockIdx.x;
    const int t = threadIdx.x;  // 128
    const float dn = g_denom[(size_t)n * Hh + (t >> 4)];
    const float v = feat[(size_t)n * Dd + t] + g_acc[(size_t)n * Dd + t] / dn;
    float s = v, s2 = v * v;
#pragma unroll
    for (int o = 16; o > 0; o >>= 1) {
        s += __shfl_xor_sync(0xffffffffu, s, o);
        s2 += __shfl_xor_sync(0xffffffffu, s2, o);
    }
    __shared__ float red[8];
    const int w = t >> 5, lane = t & 31;
    if (lane == 0) { red[w] = s; red[4 + w] = s2; }
    __syncthreads();
    if (t == 0) {
        const float S = red[0] + red[1] + red[2] + red[3];
        const float S2 = red[4] + red[5] + red[6] + red[7];
        const float mu = S * (1.f / Dd);
        const float var = S2 * (1.f / Dd) - mu * mu;
        red[0] = mu;
        red[1] = rsqrtf(var + 1e-5f);
    }
    __syncthreads();
    const float mu = red[0], r = red[1];
    y[(size_t)n * Dd + t] = (v - mu) * r * g[t] + b[t];
}

// ---------------- LN2 over last dim (128), block per node ----------------------
__global__ void ln_kernel(const float* __restrict__ x, const float* __restrict__ g,
                          const float* __restrict__ b, float* __restrict__ y) {
    const int n = blockIdx.x;
    const int t = threadIdx.x;  // 128
    const float v = x[(size_t)n * Dd + t];
    float s = v, s2 = v * v;
#pragma unroll
    for (int o = 16; o > 0; o >>= 1) {
        s += __shfl_xor_sync(0xffffffffu, s, o);
        s2 += __shfl_xor_sync(0xffffffffu, s2, o);
    }
    __shared__ float red[8];
    const int w = t >> 5, lane = t & 31;
    if (lane == 0) { red[w] = s; red[4 + w] = s2; }
    __syncthreads();
    if (t == 0) {
        const float S = red[0] + red[1] + red[2] + red[3];
        const float S2 = red[4] + red[5] + red[6] + red[7];
        const float mu = S * (1.f / Dd);
        const float var = S2 * (1.f / Dd) - mu * mu;
        red[0] = mu;
        red[1] = rsqrtf(var + 1e-5f);
    }
    __syncthreads();
    const float mu = red[0], r = red[1];
    y[(size_t)n * Dd + t] = (v - mu) * r * g[t] + b[t];
}

// ---------------- launch ----------------
extern "C" void kernel_launch(void* const* d_in, const int* in_sizes, int n_in,
                              void* d_out, int out_size) {
    const float* feat  = (const float*)d_in[0];
    const int*   src   = (const int*)d_in[1];
    const int*   dst   = (const int*)d_in[2];
    const float* Wq    = (const float*)d_in[3];
    const float* bq    = (const float*)d_in[4];
    const float* Wk    = (const float*)d_in[5];
    const float* bk    = (const float*)d_in[6];
    const float* Wv    = (const float*)d_in[7];
    const float* bv    = (const float*)d_in[8];
    const float* ln_g  = (const float*)d_in[9];
    const float* ln_b  = (const float*)d_in[10];
    const float* W1    = (const float*)d_in[11];
    const float* b1    = (const float*)d_in[12];
    const float* alpha = (const float*)d_in[13];
    const float* W2    = (const float*)d_in[14];
    const float* b2    = (const float*)d_in[15];
    float* out = (float*)d_out;

    float *pq, *pk, *pv, *prstn, *phid, *pf2;
    cudaGetSymbolAddress((void**)&pq, g_q);
    cudaGetSymbolAddress((void**)&pk, g_k);
    cudaGetSymbolAddress((void**)&pv, g_v);
    cudaGetSymbolAddress((void**)&prstn, g_rstn);
    cudaGetSymbolAddress((void**)&phid, g_hid);
    cudaGetSymbolAddress((void**)&pf2, g_f2);

    const int MB = (Nn + 127) / 128;  // 782

    init_kernel<<<(Nn * Dd + 255) / 256, 256>>>();

    gemm_tc<0><<<dim3(Dd / 64, MB), 256>>>(feat, Wq, bq, nullptr, nullptr, pq, Nn, Dd, Dd);
    gemm_tc<0><<<dim3(Dd / 64, MB), 256>>>(feat, Wk, bk, nullptr, nullptr, pk, Nn, Dd, Dd);
    gemm_tc<0><<<dim3(Dd / 64, MB), 256>>>(feat, Wv, bv, nullptr, nullptr, pv, Nn, Dd, Dd);

    const long long ethreads = (long long)Ee * 32;
    edge_fused<<<(int)((ethreads + 255) / 256), 256>>>(src, dst);

    ln1_kernel<<<Nn, 128>>>(feat, ln_g, ln_b, prstn);

    gemm_tc<1><<<dim3(Ff / 64, MB), 256>>>(prstn, W1, b1, alpha, nullptr, phid, Nn, Ff, Dd);
    gemm_tc<2><<<dim3(Dd / 64, MB), 256>>>(phid, W2, b2, nullptr, prstn, pf2, Nn, Dd, Ff);

    ln_kernel<<<Nn, 128>>>(pf2, ln_g, ln_b, out);
}

// round 8
// speedup vs baseline: 1.7274x; 1.0633x over previous
#include <cuda_runtime.h>
#include <mma.h>
#include <math.h>

using namespace nvcuda;

#define Nn 100000
#define Ee 1600000
#define Dd 128
#define Hh 8
#define Ff 512
#define QKV 384

// ---------------- scratch (static device globals; no allocation) ----------------
__device__ float g_qkv[(size_t)Nn * QKV];   // [q | k | v] per node
__device__ float g_wqkv[(size_t)Dd * QKV];  // [Wq | Wk | Wv]
__device__ float g_bqkv[QKV];
__device__ float g_acc[(size_t)Nn * Dd];    // sum over edges of ex * v[src]
__device__ float g_denom[(size_t)Nn * Hh];  // sum over edges of ex
__device__ float g_rstn[(size_t)Nn * Dd];   // post-LN1
__device__ float g_hid[(size_t)Nn * Ff];    // FFN hidden

// ---------------- init: acc = 0, denom = 0 (every graph replay) ----------------
__global__ void init_kernel() {
    int i = blockIdx.x * blockDim.x + threadIdx.x;
    if (i < Nn * Dd) g_acc[i] = 0.f;
    if (i < Nn * Hh) g_denom[i] = 0.f;
}

// ---------------- concat Wq|Wk|Wv and biases ----------------
__global__ void concat_w(const float* __restrict__ Wq, const float* __restrict__ Wk,
                         const float* __restrict__ Wv, const float* __restrict__ bq,
                         const float* __restrict__ bk, const float* __restrict__ bv) {
    const int i = blockIdx.x * blockDim.x + threadIdx.x;
    if (i < Dd * QKV) {
        const int r = i / QKV, c = i % QKV;
        float v;
        if (c < 128)      v = Wq[r * Dd + c];
        else if (c < 256) v = Wk[r * Dd + c - 128];
        else              v = Wv[r * Dd + c - 256];
        g_wqkv[i] = v;
    }
    if (i < QKV) {
        float v;
        if (i < 128)      v = bq[i];
        else if (i < 256) v = bk[i - 128];
        else              v = bv[i - 256];
        g_bqkv[i] = v;
    }
}

// ---------------- cp.async helpers ----------------
__device__ __forceinline__ void cp_async16(void* smem, const void* gmem, int sz) {
    const unsigned s = (unsigned)__cvta_generic_to_shared(smem);
    asm volatile("cp.async.cg.shared.global [%0], [%1], 16, %2;" ::
                     "r"(s), "l"(gmem), "r"(sz));
}

// ---------------- pipelined TF32 GEMM: C = A[M,K] @ W[K,Nc] + bias ----------------
// Block tile 128x128, BK=16, 2-stage cp.async, 8 warps (warp tile 32x64).
// MODE 0: plain   1: PReLU(alpha)   2: += res   3: += res then row-LayerNorm (Nc must be 128)
struct StageBuf {
    float As[2][128][20];  // 20.5 KB
    float Bs[2][16][132];  // 16.9 KB
};
struct EpiBuf {
    float Cs[128][68];     // one 64-col half
    float rsum[128], rsq[128], mu[128], rs[128];
};
union GSmem {
    StageBuf st;
    EpiBuf ep;
};

template <int MODE>
__global__ void __launch_bounds__(256) gemm_tc(
    const float* __restrict__ A, const float* __restrict__ W,
    const float* __restrict__ bias, const float* __restrict__ alpha,
    const float* __restrict__ res, const float* __restrict__ lng,
    const float* __restrict__ lnb, float* __restrict__ C,
    int M, int Nc, int K) {
    __shared__ GSmem sm;

    const int t = threadIdx.x;
    const int w = t >> 5;
    const int warp_m = w & 3;   // 0..3 -> 32 rows
    const int warp_n = w >> 2;  // 0..1 -> 64 cols
    const int bm = blockIdx.y * 128, bn = blockIdx.x * 128;

    wmma::fragment<wmma::accumulator, 16, 16, 8, float> cf[2][4];
#pragma unroll
    for (int i = 0; i < 2; i++)
#pragma unroll
        for (int j = 0; j < 4; j++) wmma::fill_fragment(cf[i][j], 0.f);

    const int nk = K >> 4;

    // stage loader: A tile 128x16 (512 f4), B tile 16x128 (512 f4); 2 f4 each per thread
#define LOAD_STAGE(S, KK)                                                          \
    {                                                                              \
        _Pragma("unroll") for (int i = 0; i < 2; i++) {                            \
            const int idx = t + i * 256;                                           \
            const int r = idx >> 2, c = (idx & 3) * 4;                             \
            cp_async16(&sm.st.As[S][r][c], &A[(size_t)(bm + r) * K + (KK) + c],    \
                       (bm + r) < M ? 16 : 0);                                     \
        }                                                                          \
        _Pragma("unroll") for (int i = 0; i < 2; i++) {                            \
            const int idx = t + i * 256;                                           \
            const int r = idx >> 5, c = (idx & 31) * 4;                            \
            cp_async16(&sm.st.Bs[S][r][c], &W[(size_t)((KK) + r) * Nc + bn + c],   \
                       16);                                                        \
        }                                                                          \
        asm volatile("cp.async.commit_group;");                                    \
    }

    LOAD_STAGE(0, 0)

    for (int s = 0; s < nk; s++) {
        if (s + 1 < nk) {
            LOAD_STAGE((s + 1) & 1, (s + 1) * 16)
            asm volatile("cp.async.wait_group 1;");
        } else {
            asm volatile("cp.async.wait_group 0;");
        }
        __syncthreads();

        const int buf = s & 1;
#pragma unroll
        for (int ks = 0; ks < 2; ks++) {
            const int k = ks * 8;
            wmma::fragment<wmma::matrix_a, 16, 16, 8, wmma::precision::tf32, wmma::row_major> af[2];
            wmma::fragment<wmma::matrix_b, 16, 16, 8, wmma::precision::tf32, wmma::row_major> bf[4];
#pragma unroll
            for (int i = 0; i < 2; i++) {
                wmma::load_matrix_sync(af[i], &sm.st.As[buf][warp_m * 32 + i * 16][k], 20);
#pragma unroll
                for (int x = 0; x < af[i].num_elements; x++)
                    af[i].x[x] = wmma::__float_to_tf32(af[i].x[x]);
            }
#pragma unroll
            for (int j = 0; j < 4; j++) {
                wmma::load_matrix_sync(bf[j], &sm.st.Bs[buf][k][warp_n * 64 + j * 16], 132);
#pragma unroll
                for (int x = 0; x < bf[j].num_elements; x++)
                    bf[j].x[x] = wmma::__float_to_tf32(bf[j].x[x]);
            }
#pragma unroll
            for (int i = 0; i < 2; i++)
#pragma unroll
                for (int j = 0; j < 4; j++)
                    wmma::mma_sync(cf[i][j], af[i], bf[j], cf[i][j]);
        }
        __syncthreads();
    }

    // ---------------- epilogue: two 64-col halves through sm.ep.Cs ----------------
    float vals[2][8][4];  // kept only for MODE 3

    if (MODE == 3) {
        if (t < 128) { sm.ep.rsum[t] = 0.f; sm.ep.rsq[t] = 0.f; }
        __syncthreads();
    }

#pragma unroll
    for (int h = 0; h < 2; h++) {
        if (warp_n == h) {
#pragma unroll
            for (int i = 0; i < 2; i++)
#pragma unroll
                for (int j = 0; j < 4; j++)
                    wmma::store_matrix_sync(&sm.ep.Cs[warp_m * 32 + i * 16][j * 16],
                                            cf[i][j], 68, wmma::mem_row_major);
        }
        __syncthreads();

#pragma unroll
        for (int i = 0; i < 8; i++) {
            const int idx = t + i * 256;
            const int row = idx >> 4;
            const int col = (idx & 15) * 4;
            const int gcol = bn + h * 64 + col;
            const int grow = bm + row;
            float c[4];
#pragma unroll
            for (int x = 0; x < 4; x++) c[x] = sm.ep.Cs[row][col + x] + bias[gcol + x];
            if (MODE == 1) {
#pragma unroll
                for (int x = 0; x < 4; x++) {
                    const float al = alpha[gcol + x];
                    c[x] = c[x] > 0.f ? c[x] : al * c[x];
                }
            }
            if ((MODE == 2 || MODE == 3) && grow < M) {
                const float4 r4 = *(const float4*)&res[(size_t)grow * Nc + gcol];
                c[0] += r4.x; c[1] += r4.y; c[2] += r4.z; c[3] += r4.w;
            }
            if (MODE != 3) {
                if (grow < M)
                    *(float4*)&C[(size_t)grow * Nc + gcol] =
                        make_float4(c[0], c[1], c[2], c[3]);
            } else {
#pragma unroll
                for (int x = 0; x < 4; x++) vals[h][i][x] = c[x];
                float ps = c[0] + c[1] + c[2] + c[3];
                float pq = c[0] * c[0] + c[1] * c[1] + c[2] * c[2] + c[3] * c[3];
#pragma unroll
                for (int o = 1; o < 16; o <<= 1) {
                    ps += __shfl_xor_sync(0xffffffffu, ps, o, 16);
                    pq += __shfl_xor_sync(0xffffffffu, pq, o, 16);
                }
                if ((t & 15) == 0) {
                    sm.ep.rsum[row] += ps;
                    sm.ep.rsq[row] += pq;
                }
            }
        }
        __syncthreads();
    }

    if (MODE == 3) {
        // Nc == 128 == BN: full row is in this block
        if (t < 128) {
            const float mu = sm.ep.rsum[t] * (1.f / 128.f);
            const float var = sm.ep.rsq[t] * (1.f / 128.f) - mu * mu;
            sm.ep.mu[t] = mu;
            sm.ep.rs[t] = rsqrtf(var + 1e-5f);
        }
        __syncthreads();
#pragma unroll
        for (int h = 0; h < 2; h++)
#pragma unroll
            for (int i = 0; i < 8; i++) {
                const int idx = t + i * 256;
                const int row = idx >> 4;
                const int col = (idx & 15) * 4;
                const int gcol = h * 64 + col;  // bn == 0 for MODE 3
                const int grow = bm + row;
                if (grow >= M) continue;
                const float mu = sm.ep.mu[row], rsg = sm.ep.rs[row];
                float o[4];
#pragma unroll
                for (int x = 0; x < 4; x++)
                    o[x] = (vals[h][i][x] - mu) * rsg * lng[gcol + x] + lnb[gcol + x];
                *(float4*)&C[(size_t)grow * 128 + gcol] =
                    make_float4(o[0], o[1], o[2], o[3]);
            }
    }
#undef LOAD_STAGE
}

// ---------------- fused edge pass: warp per edge -------------------------------
// e[h] = <k[src], q[dst]>_head / sqrt(D); ex = exp(e)
// denom[dst,h] += ex ; acc[dst] += ex * v[src]   (softmax division deferred to LN1)
__global__ void edge_fused(const int* __restrict__ src, const int* __restrict__ dst) {
    const long long idx = (long long)blockIdx.x * blockDim.x + threadIdx.x;
    const int e = (int)(idx >> 5);
    if (e >= Ee) return;
    const int lane = (int)(idx & 31);
    const int s = src[e], d = dst[e];
    const float4 qv = *(const float4*)&g_qkv[(size_t)d * QKV + lane * 4];
    const float4 kv = *(const float4*)&g_qkv[(size_t)s * QKV + 128 + lane * 4];
    const float4 vv = *(const float4*)&g_qkv[(size_t)s * QKV + 256 + lane * 4];
    float p = kv.x * qv.x + kv.y * qv.y + kv.z * qv.z + kv.w * qv.w;
    p += __shfl_xor_sync(0xffffffffu, p, 1);
    p += __shfl_xor_sync(0xffffffffu, p, 2);  // all 4 lanes of a head hold the dot
    const float ee = __expf(p * 0.08838834764831845f);  // 1/sqrt(128)
    if ((lane & 3) == 0)
        atomicAdd(&g_denom[(size_t)d * Hh + (lane >> 2)], ee);
    float* out = &g_acc[(size_t)d * Dd + lane * 4];
    asm volatile("red.global.add.v4.f32 [%0], {%1,%2,%3,%4};" ::
                     "l"(out), "f"(vv.x * ee), "f"(vv.y * ee), "f"(vv.z * ee), "f"(vv.w * ee)
                 : "memory");
}

// ---------------- LN1: rstn = LN(feat + acc/denom) -----------------------------
__global__ void ln1_kernel(const float* __restrict__ feat, const float* __restrict__ g,
                           const float* __restrict__ b, float* __restrict__ y) {
    const int n = blockIdx.x;
    const int t = threadIdx.x;  // 128
    const float dn = g_denom[(size_t)n * Hh + (t >> 4)];
    const float v = feat[(size_t)n * Dd + t] + g_acc[(size_t)n * Dd + t] / dn;
    float s = v, s2 = v * v;
#pragma unroll
    for (int o = 16; o > 0; o >>= 1) {
        s += __shfl_xor_sync(0xffffffffu, s, o);
        s2 += __shfl_xor_sync(0xffffffffu, s2, o);
    }
    __shared__ float red[8];
    const int w = t >> 5, lane = t & 31;
    if (lane == 0) { red[w] = s; red[4 + w] = s2; }
    __syncthreads();
    if (t == 0) {
        const float S = red[0] + red[1] + red[2] + red[3];
        const float S2 = red[4] + red[5] + red[6] + red[7];
        const float mu = S * (1.f / Dd);
        const float var = S2 * (1.f / Dd) - mu * mu;
        red[0] = mu;
        red[1] = rsqrtf(var + 1e-5f);
    }
    __syncthreads();
    const float mu = red[0], r = red[1];
    y[(size_t)n * Dd + t] = (v - mu) * r * g[t] + b[t];
}

// ---------------- launch ----------------
extern "C" void kernel_launch(void* const* d_in, const int* in_sizes, int n_in,
                              void* d_out, int out_size) {
    const float* feat  = (const float*)d_in[0];
    const int*   src   = (const int*)d_in[1];
    const int*   dst   = (const int*)d_in[2];
    const float* Wq    = (const float*)d_in[3];
    const float* bq    = (const float*)d_in[4];
    const float* Wk    = (const float*)d_in[5];
    const float* bk    = (const float*)d_in[6];
    const float* Wv    = (const float*)d_in[7];
    const float* bv    = (const float*)d_in[8];
    const float* ln_g  = (const float*)d_in[9];
    const float* ln_b  = (const float*)d_in[10];
    const float* W1    = (const float*)d_in[11];
    const float* b1    = (const float*)d_in[12];
    const float* alpha = (const float*)d_in[13];
    const float* W2    = (const float*)d_in[14];
    const float* b2    = (const float*)d_in[15];
    float* out = (float*)d_out;

    float *pqkv, *pwqkv, *pbqkv, *prstn, *phid;
    cudaGetSymbolAddress((void**)&pqkv, g_qkv);
    cudaGetSymbolAddress((void**)&pwqkv, g_wqkv);
    cudaGetSymbolAddress((void**)&pbqkv, g_bqkv);
    cudaGetSymbolAddress((void**)&prstn, g_rstn);
    cudaGetSymbolAddress((void**)&phid, g_hid);

    const int MB = (Nn + 127) / 128;  // 782

    init_kernel<<<(Nn * Dd + 255) / 256, 256>>>();
    concat_w<<<(Dd * QKV + 255) / 256, 256>>>(Wq, Wk, Wv, bq, bk, bv);

    // fused QKV projection: [Nn,128] @ [128,384]
    gemm_tc<0><<<dim3(QKV / 128, MB), 256>>>(feat, pwqkv, pbqkv, nullptr, nullptr,
                                             nullptr, nullptr, pqkv, Nn, QKV, Dd);

    const long long ethreads = (long long)Ee * 32;
    edge_fused<<<(int)((ethreads + 255) / 256), 256>>>(src, dst);

    ln1_kernel<<<Nn, 128>>>(feat, ln_g, ln_b, prstn);

    // FFN: [Nn,128]@[128,512] + PReLU, then [Nn,512]@[512,128] + res + LN2 -> out
    gemm_tc<1><<<dim3(Ff / 128, MB), 256>>>(prstn, W1, b1, alpha, nullptr,
                                            nullptr, nullptr, phid, Nn, Ff, Dd);
    gemm_tc<3><<<dim3(1, MB), 256>>>(phid, W2, b2, nullptr, prstn,
                                     ln_g, ln_b, out, Nn, Dd, Ff);
}

// round 9
// speedup vs baseline: 3.4744x; 2.0113x over previous
#include <cuda_runtime.h>
#include <cuda_fp16.h>
#include <mma.h>
#include <math.h>

using namespace nvcuda;

#define Nn 100000
#define Ee 1600000
#define Dd 128
#define Hh 8
#define Ff 512
#define QKV 384

// ---------------- scratch (static device globals; no allocation) ----------------
__device__ __half g_feat_h[(size_t)Nn * Dd];   // fp16 copy of feat (GEMM A)
__device__ __half g_qkv_h[(size_t)Nn * QKV];   // [q|k|v] fp16 per node
__device__ __half g_wqkv_h[(size_t)Dd * QKV];  // [Wq|Wk|Wv] fp16
__device__ __half g_w1h[(size_t)Dd * Ff];
__device__ __half g_w2h[(size_t)Ff * Dd];
__device__ float  g_bqkv[QKV];
__device__ float  g_acc[(size_t)Nn * Dd];      // fp32: sum_e ex * v[src]
__device__ float  g_denom[(size_t)Nn * Hh];    // fp32: sum_e ex
__device__ float  g_rstn_f[(size_t)Nn * Dd];   // post-LN1 fp32 (residual for LN2)
__device__ __half g_rstn_h[(size_t)Nn * Dd];   // post-LN1 fp16 (FFN1 A)
__device__ __half g_hid_h[(size_t)Nn * Ff];    // FFN hidden fp16 (FFN2 A)

// ---------------- init: acc=0, denom=0, feat->fp16 (every replay) --------------
__global__ void init_kernel(const float* __restrict__ feat) {
    int i = blockIdx.x * blockDim.x + threadIdx.x;
    if (i < Nn * Dd) {
        g_acc[i] = 0.f;
        g_feat_h[i] = __float2half(feat[i]);
    }
    if (i < Nn * Hh) g_denom[i] = 0.f;
}

// ---------------- weight conversion / concat ----------------
__global__ void conv_w(const float* __restrict__ Wq, const float* __restrict__ Wk,
                       const float* __restrict__ Wv, const float* __restrict__ bq,
                       const float* __restrict__ bk, const float* __restrict__ bv,
                       const float* __restrict__ W1, const float* __restrict__ W2) {
    const int i = blockIdx.x * blockDim.x + threadIdx.x;
    if (i < Dd * QKV) {
        const int r = i / QKV, c = i % QKV;
        float v;
        if (c < 128)      v = Wq[r * Dd + c];
        else if (c < 256) v = Wk[r * Dd + c - 128];
        else              v = Wv[r * Dd + c - 256];
        g_wqkv_h[i] = __float2half(v);
    }
    if (i < Dd * Ff) g_w1h[i] = __float2half(W1[i]);
    if (i < Ff * Dd) g_w2h[i] = __float2half(W2[i]);
    if (i < QKV) {
        float v;
        if (i < 128)      v = bq[i];
        else if (i < 256) v = bk[i - 128];
        else              v = bv[i - 256];
        g_bqkv[i] = v;
    }
}

// ---------------- cp.async helper ----------------
__device__ __forceinline__ void cp_async16(void* smem, const void* gmem, int sz) {
    const unsigned s = (unsigned)__cvta_generic_to_shared(smem);
    asm volatile("cp.async.cg.shared.global [%0], [%1], 16, %2;" ::
                     "r"(s), "l"(gmem), "r"(sz));
}

// ---------------- pipelined fp16 GEMM: C = A[M,K] @ W[K,Nc] + bias ----------------
// Block tile 128x128, BK=32, 2-stage cp.async, 8 warps (warp tile 32x64). fp32 accum.
// MODE 0: plain -> fp16 C    1: PReLU -> fp16 C    3: +res(fp32) -> row-LN -> fp32 C
struct StageBuf {
    __half As[2][128][40];   // 20.0 KB, row = 80B (16B-mult)
    __half Bs[2][32][136];   // 17.0 KB, row = 272B (16B-mult)
};
struct EpiBuf {
    float Cs[128][68];       // one 64-col half: 34.8 KB
    float rsum[128], rsq[128], mu[128], rs[128];
};
union GSmem {
    StageBuf st;
    EpiBuf ep;
};

template <int MODE>
__global__ void __launch_bounds__(256) gemm_h(
    const __half* __restrict__ A, const __half* __restrict__ W,
    const float* __restrict__ bias, const float* __restrict__ alpha,
    const float* __restrict__ res, const float* __restrict__ lng,
    const float* __restrict__ lnb, void* __restrict__ Cout,
    int M, int Nc, int K) {
    __shared__ GSmem sm;

    const int t = threadIdx.x;
    const int w = t >> 5;
    const int warp_m = w & 3;   // 0..3 -> 32 rows
    const int warp_n = w >> 2;  // 0..1 -> 64 cols
    const int bm = blockIdx.y * 128, bn = blockIdx.x * 128;

    wmma::fragment<wmma::accumulator, 16, 16, 16, float> cf[2][4];
#pragma unroll
    for (int i = 0; i < 2; i++)
#pragma unroll
        for (int j = 0; j < 4; j++) wmma::fill_fragment(cf[i][j], 0.f);

    const int nk = K >> 5;

    // A tile 128x32 halves: 512 x 16B chunks; B tile 32x128 halves: 512 chunks
#define LOAD_STAGE(S, KK)                                                           \
    {                                                                               \
        _Pragma("unroll") for (int i = 0; i < 2; i++) {                             \
            const int idx = t + i * 256;                                            \
            const int r = idx >> 2, c = (idx & 3) * 8;                              \
            cp_async16(&sm.st.As[S][r][c], &A[(size_t)(bm + r) * K + (KK) + c],     \
                       (bm + r) < M ? 16 : 0);                                      \
        }                                                                           \
        _Pragma("unroll") for (int i = 0; i < 2; i++) {                             \
            const int idx = t + i * 256;                                            \
            const int r = idx >> 4, c = (idx & 15) * 8;                             \
            cp_async16(&sm.st.Bs[S][r][c], &W[(size_t)((KK) + r) * Nc + bn + c],    \
                       16);                                                         \
        }                                                                           \
        asm volatile("cp.async.commit_group;");                                     \
    }

    LOAD_STAGE(0, 0)

    for (int s = 0; s < nk; s++) {
        if (s + 1 < nk) {
            LOAD_STAGE((s + 1) & 1, (s + 1) * 32)
            asm volatile("cp.async.wait_group 1;");
        } else {
            asm volatile("cp.async.wait_group 0;");
        }
        __syncthreads();

        const int buf = s & 1;
#pragma unroll
        for (int ks = 0; ks < 2; ks++) {
            const int k = ks * 16;
            wmma::fragment<wmma::matrix_a, 16, 16, 16, __half, wmma::row_major> af[2];
            wmma::fragment<wmma::matrix_b, 16, 16, 16, __half, wmma::row_major> bf[4];
#pragma unroll
            for (int i = 0; i < 2; i++)
                wmma::load_matrix_sync(af[i], &sm.st.As[buf][warp_m * 32 + i * 16][k], 40);
#pragma unroll
            for (int j = 0; j < 4; j++)
                wmma::load_matrix_sync(bf[j], &sm.st.Bs[buf][k][warp_n * 64 + j * 16], 136);
#pragma unroll
            for (int i = 0; i < 2; i++)
#pragma unroll
                for (int j = 0; j < 4; j++)
                    wmma::mma_sync(cf[i][j], af[i], bf[j], cf[i][j]);
        }
        __syncthreads();
    }

    // ---------------- epilogue: two 64-col halves through sm.ep.Cs ----------------
    float vals[2][8][4];  // live only for MODE 3

    if (MODE == 3) {
        if (t < 128) { sm.ep.rsum[t] = 0.f; sm.ep.rsq[t] = 0.f; }
        __syncthreads();
    }

#pragma unroll
    for (int h = 0; h < 2; h++) {
        if (warp_n == h) {
#pragma unroll
            for (int i = 0; i < 2; i++)
#pragma unroll
                for (int j = 0; j < 4; j++)
                    wmma::store_matrix_sync(&sm.ep.Cs[warp_m * 32 + i * 16][j * 16],
                                            cf[i][j], 68, wmma::mem_row_major);
        }
        __syncthreads();

#pragma unroll
        for (int i = 0; i < 8; i++) {
            const int idx = t + i * 256;
            const int row = idx >> 4;
            const int col = (idx & 15) * 4;
            const int gcol = bn + h * 64 + col;
            const int grow = bm + row;
            float c[4];
#pragma unroll
            for (int x = 0; x < 4; x++) c[x] = sm.ep.Cs[row][col + x] + bias[gcol + x];
            if (MODE == 1) {
#pragma unroll
                for (int x = 0; x < 4; x++) {
                    const float al = alpha[gcol + x];
                    c[x] = c[x] > 0.f ? c[x] : al * c[x];
                }
            }
            if (MODE == 3 && grow < M) {
                const float4 r4 = *(const float4*)&res[(size_t)grow * Nc + gcol];
                c[0] += r4.x; c[1] += r4.y; c[2] += r4.z; c[3] += r4.w;
            }
            if (MODE != 3) {
                if (grow < M) {
                    __half2 h01 = __floats2half2_rn(c[0], c[1]);
                    __half2 h23 = __floats2half2_rn(c[2], c[3]);
                    uint2 pk;
                    pk.x = *(unsigned*)&h01;
                    pk.y = *(unsigned*)&h23;
                    *(uint2*)&((__half*)Cout)[(size_t)grow * Nc + gcol] = pk;
                }
            } else {
#pragma unroll
                for (int x = 0; x < 4; x++) vals[h][i][x] = c[x];
                float ps = c[0] + c[1] + c[2] + c[3];
                float pq = c[0] * c[0] + c[1] * c[1] + c[2] * c[2] + c[3] * c[3];
#pragma unroll
                for (int o = 1; o < 16; o <<= 1) {
                    ps += __shfl_xor_sync(0xffffffffu, ps, o, 16);
                    pq += __shfl_xor_sync(0xffffffffu, pq, o, 16);
                }
                if ((t & 15) == 0) {
                    sm.ep.rsum[row] += ps;
                    sm.ep.rsq[row] += pq;
                }
            }
        }
        __syncthreads();
    }

    if (MODE == 3) {
        if (t < 128) {
            const float mu = sm.ep.rsum[t] * (1.f / 128.f);
            const float var = sm.ep.rsq[t] * (1.f / 128.f) - mu * mu;
            sm.ep.mu[t] = mu;
            sm.ep.rs[t] = rsqrtf(var + 1e-5f);
        }
        __syncthreads();
        float* C = (float*)Cout;
#pragma unroll
        for (int h = 0; h < 2; h++)
#pragma unroll
            for (int i = 0; i < 8; i++) {
                const int idx = t + i * 256;
                const int row = idx >> 4;
                const int col = (idx & 15) * 4;
                const int gcol = h * 64 + col;  // bn == 0 in MODE 3
                const int grow = bm + row;
                if (grow >= M) continue;
                const float mu = sm.ep.mu[row], rsg = sm.ep.rs[row];
                float o[4];
#pragma unroll
                for (int x = 0; x < 4; x++)
                    o[x] = (vals[h][i][x] - mu) * rsg * lng[gcol + x] + lnb[gcol + x];
                *(float4*)&C[(size_t)grow * 128 + gcol] =
                    make_float4(o[0], o[1], o[2], o[3]);
            }
    }
#undef LOAD_STAGE
}

// ---------------- fused edge pass: warp per edge, fp16 gathers ------------------
// e[h] = <k[src], q[dst]>_head / sqrt(D); ex = exp(e)
// denom[dst,h] += ex ; acc[dst] += ex * v[src]   (softmax division deferred to LN1)
__global__ void edge_fused(const int* __restrict__ src, const int* __restrict__ dst) {
    const long long idx = (long long)blockIdx.x * blockDim.x + threadIdx.x;
    const int e = (int)(idx >> 5);
    if (e >= Ee) return;
    const int lane = (int)(idx & 31);
    const int s = src[e], d = dst[e];

    const uint2 qr = *(const uint2*)&g_qkv_h[(size_t)d * QKV + lane * 4];
    const uint2 kr = *(const uint2*)&g_qkv_h[(size_t)s * QKV + 128 + lane * 4];
    const uint2 vr = *(const uint2*)&g_qkv_h[(size_t)s * QKV + 256 + lane * 4];
    const float2 q0 = __half22float2(*(const __half2*)&qr.x);
    const float2 q1 = __half22float2(*(const __half2*)&qr.y);
    const float2 k0 = __half22float2(*(const __half2*)&kr.x);
    const float2 k1 = __half22float2(*(const __half2*)&kr.y);
    const float2 v0 = __half22float2(*(const __half2*)&vr.x);
    const float2 v1 = __half22float2(*(const __half2*)&vr.y);

    float p = k0.x * q0.x + k0.y * q0.y + k1.x * q1.x + k1.y * q1.y;
    p += __shfl_xor_sync(0xffffffffu, p, 1);
    p += __shfl_xor_sync(0xffffffffu, p, 2);  // all 4 lanes of a head hold the dot
    const float ee = __expf(p * 0.08838834764831845f);  // 1/sqrt(128)
    if ((lane & 3) == 0)
        atomicAdd(&g_denom[(size_t)d * Hh + (lane >> 2)], ee);
    float* out = &g_acc[(size_t)d * Dd + lane * 4];
    asm volatile("red.global.add.v4.f32 [%0], {%1,%2,%3,%4};" ::
                     "l"(out), "f"(v0.x * ee), "f"(v0.y * ee), "f"(v1.x * ee), "f"(v1.y * ee)
                 : "memory");
}

// ---------------- LN1: rstn = LN(feat + acc/denom), fp32 + fp16 out -------------
__global__ void ln1_kernel(const float* __restrict__ feat, const float* __restrict__ g,
                           const float* __restrict__ b) {
    const int n = blockIdx.x;
    const int t = threadIdx.x;  // 128
    const float dn = g_denom[(size_t)n * Hh + (t >> 4)];
    const float v = feat[(size_t)n * Dd + t] + g_acc[(size_t)n * Dd + t] / dn;
    float s = v, s2 = v * v;
#pragma unroll
    for (int o = 16; o > 0; o >>= 1) {
        s += __shfl_xor_sync(0xffffffffu, s, o);
        s2 += __shfl_xor_sync(0xffffffffu, s2, o);
    }
    __shared__ float red[8];
    const int w = t >> 5, lane = t & 31;
    if (lane == 0) { red[w] = s; red[4 + w] = s2; }
    __syncthreads();
    if (t == 0) {
        const float S = red[0] + red[1] + red[2] + red[3];
        const float S2 = red[4] + red[5] + red[6] + red[7];
        const float mu = S * (1.f / Dd);
        const float var = S2 * (1.f / Dd) - mu * mu;
        red[0] = mu;
        red[1] = rsqrtf(var + 1e-5f);
    }
    __syncthreads();
    const float mu = red[0], r = red[1];
    const float y = (v - mu) * r * g[t] + b[t];
    g_rstn_f[(size_t)n * Dd + t] = y;
    g_rstn_h[(size_t)n * Dd + t] = __float2half(y);
}

// ---------------- launch ----------------
extern "C" void kernel_launch(void* const* d_in, const int* in_sizes, int n_in,
                              void* d_out, int out_size) {
    const float* feat  = (const float*)d_in[0];
    const int*   src   = (const int*)d_in[1];
    const int*   dst   = (const int*)d_in[2];
    const float* Wq    = (const float*)d_in[3];
    const float* bq    = (const float*)d_in[4];
    const float* Wk    = (const float*)d_in[5];
    const float* bk    = (const float*)d_in[6];
    const float* Wv    = (const float*)d_in[7];
    const float* bv    = (const float*)d_in[8];
    const float* ln_g  = (const float*)d_in[9];
    const float* ln_b  = (const float*)d_in[10];
    const float* W1    = (const float*)d_in[11];
    const float* b1    = (const float*)d_in[12];
    const float* alpha = (const float*)d_in[13];
    const float* W2    = (const float*)d_in[14];
    const float* b2    = (const float*)d_in[15];
    float* out = (float*)d_out;

    __half *pfh, *pqkv, *pwqkv, *pw1, *pw2, *prsth, *phid;
    float *pbqkv, *prstf;
    cudaGetSymbolAddress((void**)&pfh, g_feat_h);
    cudaGetSymbolAddress((void**)&pqkv, g_qkv_h);
    cudaGetSymbolAddress((void**)&pwqkv, g_wqkv_h);
    cudaGetSymbolAddress((void**)&pw1, g_w1h);
    cudaGetSymbolAddress((void**)&pw2, g_w2h);
    cudaGetSymbolAddress((void**)&pbqkv, g_bqkv);
    cudaGetSymbolAddress((void**)&prstf, g_rstn_f);
    cudaGetSymbolAddress((void**)&prsth, g_rstn_h);
    cudaGetSymbolAddress((void**)&phid, g_hid_h);

    const int MB = (Nn + 127) / 128;  // 782

    init_kernel<<<(Nn * Dd + 255) / 256, 256>>>(feat);
    conv_w<<<(Ff * Dd + 255) / 256, 256>>>(Wq, Wk, Wv, bq, bk, bv, W1, W2);

    // fused QKV projection: [Nn,128] @ [128,384] -> fp16
    gemm_h<0><<<dim3(QKV / 128, MB), 256>>>(pfh, pwqkv, pbqkv, nullptr, nullptr,
                                            nullptr, nullptr, pqkv, Nn, QKV, Dd);

    const long long ethreads = (long long)Ee * 32;
    edge_fused<<<(int)((ethreads + 255) / 256), 256>>>(src, dst);

    ln1_kernel<<<Nn, 128>>>(feat, ln_g, ln_b);

    // FFN: [Nn,128]@[128,512] + PReLU -> fp16, then [Nn,512]@[512,128] + res + LN2 -> out
    gemm_h<1><<<dim3(Ff / 128, MB), 256>>>(prsth, pw1, b1, alpha, nullptr,
                                           nullptr, nullptr, phid, Nn, Ff, Dd);
    gemm_h<3><<<dim3(1, MB), 256>>>(phid, pw2, b2, nullptr, prstf,
                                    ln_g, ln_b, out, Nn, Dd, Ff);
}